// round 6
// baseline (speedup 1.0000x reference)
#include <cuda_runtime.h>
#include <cuda_bf16.h>
#include <cstdint>

typedef unsigned long long u64;

// ---------------- packed fp32 + cluster helpers (sm_103a) ----------------
__device__ __forceinline__ u64 dup2(float x) {
    u64 r; asm("mov.b64 %0, {%1, %1};" : "=l"(r) : "f"(x)); return r;
}
__device__ __forceinline__ u64 fma2(u64 a, u64 b, u64 c) {
    u64 d; asm("fma.rn.f32x2 %0, %1, %2, %3;" : "=l"(d) : "l"(a), "l"(b), "l"(c));
    return d;
}
__device__ __forceinline__ void unpack2(float& lo, float& hi, u64 v) {
    asm("mov.b64 {%0, %1}, %2;" : "=f"(lo), "=f"(hi) : "l"(v));
}
__device__ __forceinline__ uint32_t smem_u32(const void* p) {
    uint32_t a;
    asm("{ .reg .u64 t0; cvta.to.shared.u64 t0, %1; cvt.u32.u64 %0, t0; }"
        : "=r"(a) : "l"(p));
    return a;
}
__device__ __forceinline__ uint32_t mapa32(uint32_t saddr, uint32_t rank) {
    uint32_t r_;
    asm("mapa.shared::cluster.u32 %0, %1, %2;" : "=r"(r_) : "r"(saddr), "r"(rank));
    return r_;
}
__device__ __forceinline__ void st_cluster_v4(uint32_t addr, float4 v) {
    asm volatile("st.shared::cluster.v4.f32 [%0], {%1,%2,%3,%4};"
                 :: "r"(addr), "f"(v.x), "f"(v.y), "f"(v.z), "f"(v.w) : "memory");
}
__device__ __forceinline__ void mbar_init(uint32_t addr, uint32_t count) {
    asm volatile("mbarrier.init.shared.b64 [%0], %1;" :: "r"(addr), "r"(count) : "memory");
}
__device__ __forceinline__ void mbar_arrive_remote(uint32_t raddr) {
    asm volatile("mbarrier.arrive.shared::cluster.b64 _, [%0];" :: "r"(raddr) : "memory");
}
__device__ __forceinline__ void mbar_wait_cluster(uint32_t mbar, uint32_t parity) {
    asm volatile(
        "{\n\t"
        ".reg .pred P;\n\t"
        "MW_%=:\n\t"
        "mbarrier.try_wait.parity.acquire.cluster.shared::cta.b64 P, [%0], %1, 0x989680;\n\t"
        "@P bra.uni MD_%=;\n\t"
        "bra.uni MW_%=;\n\t"
        "MD_%=:\n\t"
        "}"
        :: "r"(mbar), "r"(parity) : "memory");
}
__device__ __forceinline__ uint32_t ctarank() {
    uint32_t r; asm("mov.u32 %0, %%cluster_ctarank;" : "=r"(r)); return r;
}
__device__ __forceinline__ void cluster_sync_() {
    asm volatile("barrier.cluster.arrive.aligned;" ::: "memory");
    asm volatile("barrier.cluster.wait.aligned;" ::: "memory");
}

// =====================================================================
// Kernel 1: out = inputs @ W_xh + b_h   (M=65536, K=256, N=512)
// 128x128x8 tile, 256 threads, 8x8 microtile, f32x2 accumulation.
// =====================================================================
__global__ void __launch_bounds__(256)
xw_gemm_kernel(const float* __restrict__ A, const float* __restrict__ B,
               const float* __restrict__ bias, float* __restrict__ C) {
    __shared__ __align__(16) float As[8][128];
    __shared__ __align__(16) float Bs[8][128];
    const int tid = threadIdx.x;
    const int bn  = blockIdx.x;
    const int bm  = blockIdx.y;
    const int tx  = tid & 15;
    const int ty  = tid >> 4;
    const int arow = tid >> 1, acol = (tid & 1) << 2;
    const int brow = tid >> 5, bcol = (tid & 31) << 2;
    const float* Ab = A + (size_t)bm * 128 * 256;
    const float* Bb = B + bn * 128;

    u64 acc2[8][4];
#pragma unroll
    for (int i = 0; i < 8; i++)
#pragma unroll
        for (int j = 0; j < 4; j++) acc2[i][j] = 0ull;

    for (int k0 = 0; k0 < 256; k0 += 8) {
        float4 av = *(const float4*)(Ab + (size_t)arow * 256 + k0 + acol);
        As[acol + 0][arow] = av.x;
        As[acol + 1][arow] = av.y;
        As[acol + 2][arow] = av.z;
        As[acol + 3][arow] = av.w;
        *(float4*)&Bs[brow][bcol] =
            *(const float4*)(Bb + (size_t)(k0 + brow) * 512 + bcol);
        __syncthreads();
#pragma unroll
        for (int k = 0; k < 8; k++) {
            float4 a0 = *(const float4*)&As[k][ty * 8];
            float4 a1 = *(const float4*)&As[k][ty * 8 + 4];
            const u64* bp = (const u64*)&Bs[k][tx * 8];
            u64 b2[4];
#pragma unroll
            for (int j = 0; j < 4; j++) b2[j] = bp[j];
            u64 ad[8];
            ad[0] = dup2(a0.x); ad[1] = dup2(a0.y);
            ad[2] = dup2(a0.z); ad[3] = dup2(a0.w);
            ad[4] = dup2(a1.x); ad[5] = dup2(a1.y);
            ad[6] = dup2(a1.z); ad[7] = dup2(a1.w);
#pragma unroll
            for (int i = 0; i < 8; i++)
#pragma unroll
                for (int j = 0; j < 4; j++)
                    acc2[i][j] = fma2(ad[i], b2[j], acc2[i][j]);
        }
        __syncthreads();
    }

    float bi[8];
#pragma unroll
    for (int j = 0; j < 8; j++) bi[j] = bias[bn * 128 + tx * 8 + j];
#pragma unroll
    for (int i = 0; i < 8; i++) {
        size_t row = (size_t)bm * 128 + ty * 8 + i;
        float* cp = C + row * 512 + bn * 128 + tx * 8;
        float v[8];
#pragma unroll
        for (int j = 0; j < 4; j++) unpack2(v[2 * j], v[2 * j + 1], acc2[i][j]);
#pragma unroll
        for (int j = 0; j < 8; j++) v[j] += bi[j];
        *(float4*)(cp + 0) = make_float4(v[0], v[1], v[2], v[3]);
        *(float4*)(cp + 4) = make_float4(v[4], v[5], v[6], v[7]);
    }
}

// =====================================================================
// Kernel 2: recurrence. 16 clusters x 8 CTAs x 512 threads.
// CTA rank r holds W_hh[:, r*64 .. r*64+64) in SMEM (128 KB).
// h replicated per CTA, layout hb[2][4][520] (b-major, padded), filled
// each step via DSMEM vector stores + per-buffer mbarrier (no
// barrier.cluster in the loop; double buffer + data dependency gives
// backpressure).
// =====================================================================
#define HB_BSTRIDE 520
#define WS_OFF   0
#define HB_OFF   32768                       // floats; [2][4][520] = 4160
#define RED_OFF  (HB_OFF + 4160)             // 36928; 64 rows x 66 floats
#define STG_OFF  (RED_OFF + 4224)            // 41152; [4][64]
#define MBAR_OFF (STG_OFF + 256)             // 41408 floats -> byte 165632
#define K2_SMEM_BYTES (165632 + 32)

__global__ void __launch_bounds__(512, 1) __cluster_dims__(8, 1, 1)
rnn_rec_kernel(const float* __restrict__ W_hh, float* __restrict__ out) {
    extern __shared__ __align__(16) float smem[];
    float* Ws  = smem + WS_OFF;
    float* hb  = smem + HB_OFF;
    float* red = smem + RED_OFF;
    float* stg = smem + STG_OFF;

    const int tid = threadIdx.x;
    const uint32_t r = ctarank();
    const int b0 = (int)(blockIdx.x >> 3) * 4;

    // W slice: Ws[k][c] = W_hh[k*512 + r*64 + c]  (k=0..511, c=0..63)
    {
        float4* Ws4 = (float4*)Ws;
        const float4* Wg4 = (const float4*)W_hh;
        for (int i = tid; i < 512 * 16; i += 512) {
            int k = i >> 4, c4 = i & 15;
            Ws4[i] = Wg4[k * 128 + (int)r * 16 + c4];
        }
    }
    for (int i = tid; i < 2 * 4 * HB_BSTRIDE; i += 512) hb[i] = 0.0f;
    const uint32_t mbar_s = smem_u32(smem + MBAR_OFF);
    if (tid == 0) { mbar_init(mbar_s, 16); mbar_init(mbar_s + 8, 16); }
    __syncthreads();
    cluster_sync_();

    // k-loop mapping: warp w owns k in [32w, 32w+32); thread (cg,b):
    // cols {4cg..4cg+3} and {32+4cg..32+4cg+3} for batch b.
    const int w  = tid >> 5;
    const int ln = tid & 31;
    const int cg = ln & 7;
    const int b  = ln >> 3;
    // reducer mapping (tid < 256): col rc, batch rb (contiguous cols/warp)
    const int rc = tid & 63;
    const int rb = tid >> 6;

    const uint32_t hb_s = smem_u32(hb);
    const bool sender = (w >= 14) && (ln < 8);
    uint32_t rem_hb = 0, rem_mb = 0;
    if (sender) {
        rem_hb = mapa32(hb_s, (uint32_t)ln);
        rem_mb = mapa32(mbar_s, (uint32_t)ln);
    }
    const int send_b0 = (w - 14) * 2;

    u64* redu = (u64*)red;
    const int redw = (w * 4 + b) * 33 + 2 * cg;  // u64 index
    const size_t obase = ((size_t)(b0 + rb) * 1024) * 512 + (size_t)r * 64 + rc;

    int ph0 = 0, ph1 = 0;

    for (int t = 0; t < 1024; t++) {
        const int j  = t & 1;       // buffer written this step (h_t)
        const int jr = j ^ 1;       // buffer read this step (h_{t-1})
        if (t > 0) {
            if (jr == 0) { mbar_wait_cluster(mbar_s, ph0);     ph0 ^= 1; }
            else         { mbar_wait_cluster(mbar_s + 8, ph1); ph1 ^= 1; }
        }

        float xw_v = 0.0f;
        size_t oidx = 0;
        if (tid < 256) { oidx = obase + (size_t)t * 512; xw_v = out[oidx]; }

        // ---- split-K GEMV: 8 cols x 1 batch per thread, packed pairs ----
        u64 a0 = 0ull, a1 = 0ull, a2 = 0ull, a3 = 0ull;
        const float* hrow = hb + (jr * 4 + b) * HB_BSTRIDE + w * 32;
        const ulonglong2* Wk = (const ulonglong2*)(Ws + (w * 32) * 64);
#pragma unroll 2
        for (int blk = 0; blk < 8; blk++) {
            float hv[4];
            *(float4*)hv = *(const float4*)(hrow + blk * 4);
#pragma unroll
            for (int e = 0; e < 4; e++) {
                const ulonglong2* row = Wk + (blk * 4 + e) * 16;
                ulonglong2 wA = row[cg];
                ulonglong2 wB = row[8 + cg];
                u64 hd = dup2(hv[e]);
                a0 = fma2(wA.x, hd, a0);
                a1 = fma2(wA.y, hd, a1);
                a2 = fma2(wB.x, hd, a2);
                a3 = fma2(wB.y, hd, a3);
            }
        }
        redu[redw]      = a0;
        redu[redw + 1]  = a1;
        redu[redw + 16] = a2;
        redu[redw + 17] = a3;
        __syncthreads();

        // ---- reduce 16 partials + xw, tanh, store ----
        if (tid < 256) {
            float s = xw_v;
#pragma unroll
            for (int ww = 0; ww < 16; ww++)
                s += red[(ww * 4 + rb) * 66 + rc];
            float h = tanhf(s);
            out[oidx] = h;
            stg[rb * 64 + rc] = h;
        }
        __syncthreads();

        // ---- broadcast slice to all 8 ranks (2 warps x 8 lanes) ----
        if (sender && t < 1023) {
#pragma unroll
            for (int bb = 0; bb < 2; bb++) {
                const float4* src = (const float4*)(stg + (send_b0 + bb) * 64);
                uint32_t dst = rem_hb +
                    (uint32_t)(((j * 4 + send_b0 + bb) * HB_BSTRIDE + (int)r * 64) * 4);
#pragma unroll
                for (int i = 0; i < 16; i++)
                    st_cluster_v4(dst + (uint32_t)i * 16, src[i]);
            }
            mbar_arrive_remote(rem_mb + (uint32_t)j * 8);
        }
    }
    cluster_sync_();
}

// =====================================================================
extern "C" void kernel_launch(void* const* d_in, const int* in_sizes, int n_in,
                              void* d_out, int out_size) {
    const float* inputs = (const float*)d_in[0];  // (64,1024,256)
    const float* W_xh   = (const float*)d_in[1];  // (256,512)
    const float* W_hh   = (const float*)d_in[2];  // (512,512)
    const float* b_h    = (const float*)d_in[3];  // (512,)
    float* out = (float*)d_out;                   // (64,1024,512)

    cudaFuncSetAttribute(rnn_rec_kernel,
                         cudaFuncAttributeMaxDynamicSharedMemorySize,
                         K2_SMEM_BYTES);

    dim3 g1(4, 512);
    xw_gemm_kernel<<<g1, 256>>>(inputs, W_xh, b_h, out);

    rnn_rec_kernel<<<128, 512, K2_SMEM_BYTES>>>(W_hh, out);
}

// round 7
// speedup vs baseline: 1.0680x; 1.0680x over previous
#include <cuda_runtime.h>
#include <cuda_bf16.h>
#include <cstdint>

typedef unsigned long long u64;

// ---------------- packed fp32 + cluster helpers (sm_103a) ----------------
__device__ __forceinline__ u64 dup2(float x) {
    u64 r; asm("mov.b64 %0, {%1, %1};" : "=l"(r) : "f"(x)); return r;
}
__device__ __forceinline__ u64 fma2(u64 a, u64 b, u64 c) {
    u64 d; asm("fma.rn.f32x2 %0, %1, %2, %3;" : "=l"(d) : "l"(a), "l"(b), "l"(c));
    return d;
}
__device__ __forceinline__ void unpack2(float& lo, float& hi, u64 v) {
    asm("mov.b64 {%0, %1}, %2;" : "=f"(lo), "=f"(hi) : "l"(v));
}
__device__ __forceinline__ uint32_t smem_u32(const void* p) {
    uint32_t a;
    asm("{ .reg .u64 t0; cvta.to.shared.u64 t0, %1; cvt.u32.u64 %0, t0; }"
        : "=r"(a) : "l"(p));
    return a;
}
__device__ __forceinline__ uint32_t mapa32(uint32_t saddr, uint32_t rank) {
    uint32_t r_;
    asm("mapa.shared::cluster.u32 %0, %1, %2;" : "=r"(r_) : "r"(saddr), "r"(rank));
    return r_;
}
__device__ __forceinline__ void st_cluster_v4(uint32_t addr, float4 v) {
    asm volatile("st.shared::cluster.v4.f32 [%0], {%1,%2,%3,%4};"
                 :: "r"(addr), "f"(v.x), "f"(v.y), "f"(v.z), "f"(v.w) : "memory");
}
__device__ __forceinline__ uint32_t ctarank() {
    uint32_t r; asm("mov.u32 %0, %%cluster_ctarank;" : "=r"(r)); return r;
}
__device__ __forceinline__ void cluster_arrive_() {
    asm volatile("barrier.cluster.arrive.aligned;" ::: "memory");
}
__device__ __forceinline__ void cluster_wait_() {
    asm volatile("barrier.cluster.wait.aligned;" ::: "memory");
}
__device__ __forceinline__ void cluster_sync_() {
    cluster_arrive_(); cluster_wait_();
}

// =====================================================================
// Kernel 1: out = inputs @ W_xh + b_h   (M=65536, K=256, N=512)
// 128x128x8 tile, 256 threads, 8x8 microtile, f32x2 accumulation.
// =====================================================================
__global__ void __launch_bounds__(256)
xw_gemm_kernel(const float* __restrict__ A, const float* __restrict__ B,
               const float* __restrict__ bias, float* __restrict__ C) {
    __shared__ __align__(16) float As[8][128];
    __shared__ __align__(16) float Bs[8][128];
    const int tid = threadIdx.x;
    const int bn  = blockIdx.x;
    const int bm  = blockIdx.y;
    const int tx  = tid & 15;
    const int ty  = tid >> 4;
    const int arow = tid >> 1, acol = (tid & 1) << 2;
    const int brow = tid >> 5, bcol = (tid & 31) << 2;
    const float* Ab = A + (size_t)bm * 128 * 256;
    const float* Bb = B + bn * 128;

    u64 acc2[8][4];
#pragma unroll
    for (int i = 0; i < 8; i++)
#pragma unroll
        for (int j = 0; j < 4; j++) acc2[i][j] = 0ull;

    for (int k0 = 0; k0 < 256; k0 += 8) {
        float4 av = *(const float4*)(Ab + (size_t)arow * 256 + k0 + acol);
        As[acol + 0][arow] = av.x;
        As[acol + 1][arow] = av.y;
        As[acol + 2][arow] = av.z;
        As[acol + 3][arow] = av.w;
        *(float4*)&Bs[brow][bcol] =
            *(const float4*)(Bb + (size_t)(k0 + brow) * 512 + bcol);
        __syncthreads();
#pragma unroll
        for (int k = 0; k < 8; k++) {
            float4 a0 = *(const float4*)&As[k][ty * 8];
            float4 a1 = *(const float4*)&As[k][ty * 8 + 4];
            const u64* bp = (const u64*)&Bs[k][tx * 8];
            u64 b2[4];
#pragma unroll
            for (int j = 0; j < 4; j++) b2[j] = bp[j];
            u64 ad[8];
            ad[0] = dup2(a0.x); ad[1] = dup2(a0.y);
            ad[2] = dup2(a0.z); ad[3] = dup2(a0.w);
            ad[4] = dup2(a1.x); ad[5] = dup2(a1.y);
            ad[6] = dup2(a1.z); ad[7] = dup2(a1.w);
#pragma unroll
            for (int i = 0; i < 8; i++)
#pragma unroll
                for (int j = 0; j < 4; j++)
                    acc2[i][j] = fma2(ad[i], b2[j], acc2[i][j]);
        }
        __syncthreads();
    }

    float bi[8];
#pragma unroll
    for (int j = 0; j < 8; j++) bi[j] = bias[bn * 128 + tx * 8 + j];
#pragma unroll
    for (int i = 0; i < 8; i++) {
        size_t row = (size_t)bm * 128 + ty * 8 + i;
        float* cp = C + row * 512 + bn * 128 + tx * 8;
        float v[8];
#pragma unroll
        for (int j = 0; j < 4; j++) unpack2(v[2 * j], v[2 * j + 1], acc2[i][j]);
#pragma unroll
        for (int j = 0; j < 8; j++) v[j] += bi[j];
        *(float4*)(cp + 0) = make_float4(v[0], v[1], v[2], v[3]);
        *(float4*)(cp + 4) = make_float4(v[4], v[5], v[6], v[7]);
    }
}

// =====================================================================
// Kernel 2: recurrence. 16 clusters x 8 CTAs x 256 threads.
// CTA rank r holds W_hh[:, r*64 .. r*64+64) in SMEM (128 KB).
// Per step: split-K GEMV (8 warps x 64 k), smem reduce + tanh,
// vectorized DSMEM broadcast of the 4x64 slice to all 8 ranks,
// one split cluster arrive/wait (xw prefetch in between).
// =====================================================================
#define HB_STRIDE 520
// float offsets
#define WS_OFF   0                           // [512][64]          32768
#define HB_OFF   32768                       // [2][4][520]         4160
#define RED_OFF  (HB_OFF + 4160)             // [8][4][66]          2112
#define STG_OFF  (RED_OFF + 2112)            // [4][64]              256
#define K2_FLOATS (STG_OFF + 256)
#define K2_SMEM_BYTES (K2_FLOATS * 4)        // 157,184 B

__global__ void __launch_bounds__(256, 1) __cluster_dims__(8, 1, 1)
rnn_rec_kernel(const float* __restrict__ W_hh, float* __restrict__ out) {
    extern __shared__ __align__(16) float smem[];
    float* Ws  = smem + WS_OFF;
    float* hb  = smem + HB_OFF;
    float* red = smem + RED_OFF;
    float* stg = smem + STG_OFF;

    const int tid = threadIdx.x;
    const uint32_t r = ctarank();
    const int b0 = (int)(blockIdx.x >> 3) * 4;

    // ---- load W slice: Ws[k][c] = W_hh[k*512 + r*64 + c] ----
    {
        float4* Ws4 = (float4*)Ws;
        const float4* Wg4 = (const float4*)W_hh;
        for (int i = tid; i < 512 * 16; i += 256) {
            int k = i >> 4, c4 = i & 15;
            Ws4[i] = Wg4[k * 128 + (int)r * 16 + c4];
        }
    }
    for (int i = tid; i < 2 * 4 * HB_STRIDE; i += 256) hb[i] = 0.0f;
    __syncthreads();
    cluster_sync_();

    // GEMV mapping: warp w owns k in [64w, 64w+64); thread (cg 0..7, b 0..3)
    // owns cols {4cg..4cg+3} and {32+4cg..32+4cg+3} for batch b.
    const int w  = tid >> 5;
    const int ln = tid & 31;
    const int cg = ln & 7;
    const int b  = ln >> 3;
    // reduce/output mapping: col rc (0..63), batch rb (0..3)
    const int rc = tid & 63;
    const int rb = tid >> 6;
    // broadcast mapping: float4 q of stg, two ranks per thread
    const int q  = tid & 63;
    const int qb = q >> 4, qc = (q & 15) * 4;

    const uint32_t hb_s = smem_u32(hb);
    const uint32_t remA = mapa32(hb_s, (uint32_t)(tid >> 6));
    const uint32_t remB = mapa32(hb_s, (uint32_t)((tid >> 6) + 4));

    u64* redu = (u64*)red;
    const int redw = (w * 4 + b) * 33 + 2 * cg;  // u64 index into red
    const size_t obase = ((size_t)(b0 + rb) * 1024) * 512 + (size_t)r * 64 + rc;

    const ulonglong2* Wr = (const ulonglong2*)Ws;  // 16 ull2 per k-row

    float xw_next = out[obase];  // prefetch t=0

    for (int t = 0; t < 1024; t++) {
        const int j  = t & 1;       // buffer written this step (h_t)
        const int jr = j ^ 1;       // buffer read this step (h_{t-1})
        const float xw_v = xw_next;
        const size_t oidx = obase + (size_t)t * 512;

        // ---- split-K GEMV ----
        u64 a0 = 0ull, a1 = 0ull, a2 = 0ull, a3 = 0ull;
        const float* hrow = hb + (jr * 4 + b) * HB_STRIDE + w * 64;
        const ulonglong2* Wk = Wr + (w * 64) * 16;
#pragma unroll 2
        for (int kk = 0; kk < 64; kk += 4) {
            float hv[4];
            *(float4*)hv = *(const float4*)(hrow + kk);
#pragma unroll
            for (int e = 0; e < 4; e++) {
                const ulonglong2* row = Wk + (kk + e) * 16;
                ulonglong2 wA = row[cg];
                ulonglong2 wB = row[8 + cg];
                u64 hd = dup2(hv[e]);
                a0 = fma2(wA.x, hd, a0);
                a1 = fma2(wA.y, hd, a1);
                a2 = fma2(wB.x, hd, a2);
                a3 = fma2(wB.y, hd, a3);
            }
        }
        redu[redw]      = a0;
        redu[redw + 1]  = a1;
        redu[redw + 16] = a2;
        redu[redw + 17] = a3;
        __syncthreads();

        // ---- reduce 8 partials + xw, tanh, store ----
        {
            float s = xw_v;
#pragma unroll
            for (int ww = 0; ww < 8; ww++)
                s += red[(ww * 4 + rb) * 66 + rc];
            float h = tanhf(s);
            out[oidx] = h;
            stg[rb * 64 + rc] = h;
        }
        __syncthreads();

        // ---- vectorized DSMEM broadcast + split cluster sync ----
        if (t < 1023) {
            float4 v = *(const float4*)(stg + q * 4);
            uint32_t off = (uint32_t)(((j * 4 + qb) * HB_STRIDE +
                                       (int)r * 64 + qc) * 4);
            st_cluster_v4(remA + off, v);
            st_cluster_v4(remB + off, v);
            cluster_arrive_();
            xw_next = out[oidx + 512];   // prefetch under the barrier
            cluster_wait_();
        }
    }
    cluster_sync_();
}

// =====================================================================
extern "C" void kernel_launch(void* const* d_in, const int* in_sizes, int n_in,
                              void* d_out, int out_size) {
    const float* inputs = (const float*)d_in[0];  // (64,1024,256)
    const float* W_xh   = (const float*)d_in[1];  // (256,512)
    const float* W_hh   = (const float*)d_in[2];  // (512,512)
    const float* b_h    = (const float*)d_in[3];  // (512,)
    float* out = (float*)d_out;                   // (64,1024,512)

    cudaFuncSetAttribute(rnn_rec_kernel,
                         cudaFuncAttributeMaxDynamicSharedMemorySize,
                         K2_SMEM_BYTES);

    dim3 g1(4, 512);
    xw_gemm_kernel<<<g1, 256>>>(inputs, W_xh, b_h, out);

    rnn_rec_kernel<<<128, 256, K2_SMEM_BYTES>>>(W_hh, out);
}

// round 8
// speedup vs baseline: 1.4771x; 1.3831x over previous
#include <cuda_runtime.h>
#include <cuda_bf16.h>
#include <cstdint>

typedef unsigned long long u64;

// ---------------- packed fp32 + cluster helpers (sm_103a) ----------------
__device__ __forceinline__ u64 dup2(float x) {
    u64 r; asm("mov.b64 %0, {%1, %1};" : "=l"(r) : "f"(x)); return r;
}
__device__ __forceinline__ u64 fma2(u64 a, u64 b, u64 c) {
    u64 d; asm("fma.rn.f32x2 %0, %1, %2, %3;" : "=l"(d) : "l"(a), "l"(b), "l"(c));
    return d;
}
__device__ __forceinline__ void unpack2(float& lo, float& hi, u64 v) {
    asm("mov.b64 {%0, %1}, %2;" : "=f"(lo), "=f"(hi) : "l"(v));
}
__device__ __forceinline__ uint32_t smem_u32(const void* p) {
    uint32_t a;
    asm("{ .reg .u64 t0; cvta.to.shared.u64 t0, %1; cvt.u32.u64 %0, t0; }"
        : "=r"(a) : "l"(p));
    return a;
}
__device__ __forceinline__ uint32_t mapa32(uint32_t saddr, uint32_t rank) {
    uint32_t r_;
    asm("mapa.shared::cluster.u32 %0, %1, %2;" : "=r"(r_) : "r"(saddr), "r"(rank));
    return r_;
}
__device__ __forceinline__ void st_cluster_v4(uint32_t addr, float4 v) {
    asm volatile("st.shared::cluster.v4.f32 [%0], {%1,%2,%3,%4};"
                 :: "r"(addr), "f"(v.x), "f"(v.y), "f"(v.z), "f"(v.w) : "memory");
}
__device__ __forceinline__ uint32_t ctarank() {
    uint32_t r; asm("mov.u32 %0, %%cluster_ctarank;" : "=r"(r)); return r;
}
__device__ __forceinline__ void cluster_arrive_() {
    asm volatile("barrier.cluster.arrive.aligned;" ::: "memory");
}
__device__ __forceinline__ void cluster_wait_() {
    asm volatile("barrier.cluster.wait.aligned;" ::: "memory");
}
__device__ __forceinline__ void cluster_sync_() {
    cluster_arrive_(); cluster_wait_();
}

// =====================================================================
// Kernel 1: out = inputs @ W_xh + b_h   (M=65536, K=256, N=512)
// 128x128x8 tile, 256 threads, 8x8 microtile, f32x2 accumulation.
// =====================================================================
__global__ void __launch_bounds__(256)
xw_gemm_kernel(const float* __restrict__ A, const float* __restrict__ B,
               const float* __restrict__ bias, float* __restrict__ C) {
    __shared__ __align__(16) float As[8][128];
    __shared__ __align__(16) float Bs[8][128];
    const int tid = threadIdx.x;
    const int bn  = blockIdx.x;
    const int bm  = blockIdx.y;
    const int tx  = tid & 15;
    const int ty  = tid >> 4;
    const int arow = tid >> 1, acol = (tid & 1) << 2;
    const int brow = tid >> 5, bcol = (tid & 31) << 2;
    const float* Ab = A + (size_t)bm * 128 * 256;
    const float* Bb = B + bn * 128;

    u64 acc2[8][4];
#pragma unroll
    for (int i = 0; i < 8; i++)
#pragma unroll
        for (int j = 0; j < 4; j++) acc2[i][j] = 0ull;

    for (int k0 = 0; k0 < 256; k0 += 8) {
        float4 av = *(const float4*)(Ab + (size_t)arow * 256 + k0 + acol);
        As[acol + 0][arow] = av.x;
        As[acol + 1][arow] = av.y;
        As[acol + 2][arow] = av.z;
        As[acol + 3][arow] = av.w;
        *(float4*)&Bs[brow][bcol] =
            *(const float4*)(Bb + (size_t)(k0 + brow) * 512 + bcol);
        __syncthreads();
#pragma unroll
        for (int k = 0; k < 8; k++) {
            float4 a0 = *(const float4*)&As[k][ty * 8];
            float4 a1 = *(const float4*)&As[k][ty * 8 + 4];
            const u64* bp = (const u64*)&Bs[k][tx * 8];
            u64 b2[4];
#pragma unroll
            for (int j = 0; j < 4; j++) b2[j] = bp[j];
            u64 ad[8];
            ad[0] = dup2(a0.x); ad[1] = dup2(a0.y);
            ad[2] = dup2(a0.z); ad[3] = dup2(a0.w);
            ad[4] = dup2(a1.x); ad[5] = dup2(a1.y);
            ad[6] = dup2(a1.z); ad[7] = dup2(a1.w);
#pragma unroll
            for (int i = 0; i < 8; i++)
#pragma unroll
                for (int j = 0; j < 4; j++)
                    acc2[i][j] = fma2(ad[i], b2[j], acc2[i][j]);
        }
        __syncthreads();
    }

    float bi[8];
#pragma unroll
    for (int j = 0; j < 8; j++) bi[j] = bias[bn * 128 + tx * 8 + j];
#pragma unroll
    for (int i = 0; i < 8; i++) {
        size_t row = (size_t)bm * 128 + ty * 8 + i;
        float* cp = C + row * 512 + bn * 128 + tx * 8;
        float v[8];
#pragma unroll
        for (int j = 0; j < 4; j++) unpack2(v[2 * j], v[2 * j + 1], acc2[i][j]);
#pragma unroll
        for (int j = 0; j < 8; j++) v[j] += bi[j];
        *(float4*)(cp + 0) = make_float4(v[0], v[1], v[2], v[3]);
        *(float4*)(cp + 4) = make_float4(v[4], v[5], v[6], v[7]);
    }
}

// =====================================================================
// Kernel 2: recurrence. 16 clusters x 8 CTAs x 512 threads.
// CTA rank r owns W_hh[:, r*64 .. r*64+64), held in REGISTERS:
// thread (w, lane) owns col-pair (c0,c0+1) for k in [32w, 32w+32)
// as 32 packed u64 — W never touches the crossbar in the loop.
// h kept in SMEM PRE-DUPLICATED per k: {h0,h0,h1,h1,h2,h2,h3,h3},
// so the inner loop is 2 LDS.128 (broadcast) + 4 FFMA2 per k, no MOVs.
// One vectorized DSMEM broadcast + one split cluster sync per step.
// =====================================================================
// float offsets
#define WS_OFF   0                 // [512][64] staging        32768
#define HB_OFF   32768             // [2][512][8] dup'd h       8192
#define RED_OFF  (HB_OFF + 8192)   // [16][4][33] u64 = 4224 floats
#define STG_OFF  (RED_OFF + 4224)  // [64][8] dup'd slice        512
#define K2_FLOATS (STG_OFF + 512)
#define K2_SMEM_BYTES (K2_FLOATS * 4)   // 182,784 B

__global__ void __launch_bounds__(512, 1) __cluster_dims__(8, 1, 1)
rnn_rec_kernel(const float* __restrict__ W_hh, float* __restrict__ out) {
    extern __shared__ __align__(16) float smem[];
    float* Ws  = smem + WS_OFF;
    float* hb  = smem + HB_OFF;
    float* red = smem + RED_OFF;
    float* stg = smem + STG_OFF;

    const int tid = threadIdx.x;
    const uint32_t r = ctarank();
    const int b0 = (int)(blockIdx.x >> 3) * 4;

    // ---- stage W slice into SMEM (coalesced), then lift into registers ----
    {
        float4* Ws4 = (float4*)Ws;
        const float4* Wg4 = (const float4*)W_hh;
        for (int i = tid; i < 512 * 16; i += 512) {
            int k = i >> 4, c4 = i & 15;
            Ws4[i] = Wg4[k * 128 + (int)r * 16 + c4];
        }
    }
    for (int i = tid; i < 2 * 512 * 8; i += 512) hb[i] = 0.0f;
    __syncthreads();

    const int w  = tid >> 5;           // warp: k in [32w, 32w+32)
    const int ln = tid & 31;
    const int cg = ln & 15;
    const int half = ln >> 4;
    const int c0 = half * 32 + 2 * cg; // this thread's col pair (c0, c0+1)
    const int cp = half * 16 + cg;     // col-pair index 0..31

    u64 wreg[32];
    {
        const u64* wsrc = (const u64*)(Ws + (w * 32) * 64 + c0);
#pragma unroll
        for (int kk = 0; kk < 32; kk++)
            wreg[kk] = wsrc[kk * 32];  // stride 64 floats = 32 u64
    }
    cluster_sync_();                   // hb zeroed everywhere

    // reader/output mapping (tid < 256): col rc, batch rb
    const int rc = tid & 63;
    const int rb = (tid >> 6) & 3;
    // broadcast mapping: float4 q of stg (128 of them), 2 ranks/thread
    const int q = tid & 127;

    const uint32_t hb_s = smem_u32(hb);
    const uint32_t remA = mapa32(hb_s, (uint32_t)(tid >> 7));
    const uint32_t remB = mapa32(hb_s, (uint32_t)((tid >> 7) + 4));

    u64* redu = (u64*)red;
    const size_t obase = ((size_t)(b0 + rb) * 1024) * 512 + (size_t)r * 64 + rc;
    const float4* stg4 = (const float4*)stg;

    float xw_next = (tid < 256) ? out[obase] : 0.0f;

    for (int t = 0; t < 1024; t++) {
        const int j  = t & 1;       // buffer written this step
        const int jr = j ^ 1;       // buffer read this step
        const float xw_v = xw_next;
        const size_t oidx = obase + (size_t)t * 512;

        // ---- GEMV: W from regs, dup'd h broadcast from SMEM ----
        u64 a0 = 0ull, a1 = 0ull, a2 = 0ull, a3 = 0ull;
        const ulonglong2* hp =
            (const ulonglong2*)(hb + (size_t)(jr * 512 + w * 32) * 8);
#pragma unroll
        for (int kk = 0; kk < 32; kk++) {
            ulonglong2 hA = hp[kk * 2];      // {h0,h0, h1,h1}
            ulonglong2 hB = hp[kk * 2 + 1];  // {h2,h2, h3,h3}
            u64 wk = wreg[kk];
            a0 = fma2(wk, hA.x, a0);
            a1 = fma2(wk, hA.y, a1);
            a2 = fma2(wk, hB.x, a2);
            a3 = fma2(wk, hB.y, a3);
        }
        // acc a_b = (out[c0][b], out[c0+1][b])
        redu[(w * 4 + 0) * 33 + cp] = a0;
        redu[(w * 4 + 1) * 33 + cp] = a1;
        redu[(w * 4 + 2) * 33 + cp] = a2;
        redu[(w * 4 + 3) * 33 + cp] = a3;
        __syncthreads();

        // ---- reduce 16 partials + xw, tanh, store, stage dup'd ----
        if (tid < 256) {
            float s = xw_v;
#pragma unroll
            for (int ww = 0; ww < 16; ww++)
                s += red[(ww * 4 + rb) * 66 + rc];
            float h = tanhf(s);
            out[oidx] = h;
            *(u64*)(stg + rc * 8 + rb * 2) = dup2(h);
        }
        __syncthreads();

        // ---- DSMEM broadcast of dup'd slice (2 KB) + split sync ----
        if (t < 1023) {
            float4 v = stg4[q];
            uint32_t off = (uint32_t)((j * 4096 + (int)r * 512 + q * 4) * 4);
            st_cluster_v4(remA + off, v);
            st_cluster_v4(remB + off, v);
            cluster_arrive_();
            if (tid < 256) xw_next = out[oidx + 512];  // prefetch under barrier
            cluster_wait_();
        }
    }
    cluster_sync_();
}

// =====================================================================
extern "C" void kernel_launch(void* const* d_in, const int* in_sizes, int n_in,
                              void* d_out, int out_size) {
    const float* inputs = (const float*)d_in[0];  // (64,1024,256)
    const float* W_xh   = (const float*)d_in[1];  // (256,512)
    const float* W_hh   = (const float*)d_in[2];  // (512,512)
    const float* b_h    = (const float*)d_in[3];  // (512,)
    float* out = (float*)d_out;                   // (64,1024,512)

    cudaFuncSetAttribute(rnn_rec_kernel,
                         cudaFuncAttributeMaxDynamicSharedMemorySize,
                         K2_SMEM_BYTES);

    dim3 g1(4, 512);
    xw_gemm_kernel<<<g1, 256>>>(inputs, W_xh, b_h, out);

    rnn_rec_kernel<<<128, 512, K2_SMEM_BYTES>>>(W_hh, out);
}

// round 9
// speedup vs baseline: 2.3595x; 1.5974x over previous
#include <cuda_runtime.h>
#include <cuda_bf16.h>
#include <cstdint>

typedef unsigned long long u64;

// ---------------- packed fp32 + cluster helpers (sm_103a) ----------------
__device__ __forceinline__ u64 dup2(float x) {
    u64 r; asm("mov.b64 %0, {%1, %1};" : "=l"(r) : "f"(x)); return r;
}
__device__ __forceinline__ u64 fma2(u64 a, u64 b, u64 c) {
    u64 d; asm("fma.rn.f32x2 %0, %1, %2, %3;" : "=l"(d) : "l"(a), "l"(b), "l"(c));
    return d;
}
__device__ __forceinline__ void unpack2(float& lo, float& hi, u64 v) {
    asm("mov.b64 {%0, %1}, %2;" : "=f"(lo), "=f"(hi) : "l"(v));
}
__device__ __forceinline__ uint32_t smem_u32(const void* p) {
    uint32_t a;
    asm("{ .reg .u64 t0; cvta.to.shared.u64 t0, %1; cvt.u32.u64 %0, t0; }"
        : "=r"(a) : "l"(p));
    return a;
}
__device__ __forceinline__ uint32_t mapa32(uint32_t saddr, uint32_t rank) {
    uint32_t r_;
    asm("mapa.shared::cluster.u32 %0, %1, %2;" : "=r"(r_) : "r"(saddr), "r"(rank));
    return r_;
}
__device__ __forceinline__ void st_cluster_v4(uint32_t addr, float4 v) {
    asm volatile("st.shared::cluster.v4.f32 [%0], {%1,%2,%3,%4};"
                 :: "r"(addr), "f"(v.x), "f"(v.y), "f"(v.z), "f"(v.w) : "memory");
}
__device__ __forceinline__ uint32_t ctarank() {
    uint32_t r; asm("mov.u32 %0, %%cluster_ctarank;" : "=r"(r)); return r;
}
__device__ __forceinline__ void cluster_arrive_() {
    asm volatile("barrier.cluster.arrive.aligned;" ::: "memory");
}
__device__ __forceinline__ void cluster_wait_() {
    asm volatile("barrier.cluster.wait.aligned;" ::: "memory");
}
__device__ __forceinline__ void cluster_sync_() {
    cluster_arrive_(); cluster_wait_();
}

// =====================================================================
// Kernel 1: out = inputs @ W_xh + b_h   (M=65536, K=256, N=512)
// 128x128x8 tile, 256 threads, 8x8 microtile, f32x2 accumulation.
// =====================================================================
__global__ void __launch_bounds__(256)
xw_gemm_kernel(const float* __restrict__ A, const float* __restrict__ B,
               const float* __restrict__ bias, float* __restrict__ C) {
    __shared__ __align__(16) float As[8][128];
    __shared__ __align__(16) float Bs[8][128];
    const int tid = threadIdx.x;
    const int bn  = blockIdx.x;
    const int bm  = blockIdx.y;
    const int tx  = tid & 15;
    const int ty  = tid >> 4;
    const int arow = tid >> 1, acol = (tid & 1) << 2;
    const int brow = tid >> 5, bcol = (tid & 31) << 2;
    const float* Ab = A + (size_t)bm * 128 * 256;
    const float* Bb = B + bn * 128;

    u64 acc2[8][4];
#pragma unroll
    for (int i = 0; i < 8; i++)
#pragma unroll
        for (int j = 0; j < 4; j++) acc2[i][j] = 0ull;

    for (int k0 = 0; k0 < 256; k0 += 8) {
        float4 av = *(const float4*)(Ab + (size_t)arow * 256 + k0 + acol);
        As[acol + 0][arow] = av.x;
        As[acol + 1][arow] = av.y;
        As[acol + 2][arow] = av.z;
        As[acol + 3][arow] = av.w;
        *(float4*)&Bs[brow][bcol] =
            *(const float4*)(Bb + (size_t)(k0 + brow) * 512 + bcol);
        __syncthreads();
#pragma unroll
        for (int k = 0; k < 8; k++) {
            float4 a0 = *(const float4*)&As[k][ty * 8];
            float4 a1 = *(const float4*)&As[k][ty * 8 + 4];
            const u64* bp = (const u64*)&Bs[k][tx * 8];
            u64 b2[4];
#pragma unroll
            for (int j = 0; j < 4; j++) b2[j] = bp[j];
            u64 ad[8];
            ad[0] = dup2(a0.x); ad[1] = dup2(a0.y);
            ad[2] = dup2(a0.z); ad[3] = dup2(a0.w);
            ad[4] = dup2(a1.x); ad[5] = dup2(a1.y);
            ad[6] = dup2(a1.z); ad[7] = dup2(a1.w);
#pragma unroll
            for (int i = 0; i < 8; i++)
#pragma unroll
                for (int j = 0; j < 4; j++)
                    acc2[i][j] = fma2(ad[i], b2[j], acc2[i][j]);
        }
        __syncthreads();
    }

    float bi[8];
#pragma unroll
    for (int j = 0; j < 8; j++) bi[j] = bias[bn * 128 + tx * 8 + j];
#pragma unroll
    for (int i = 0; i < 8; i++) {
        size_t row = (size_t)bm * 128 + ty * 8 + i;
        float* cp = C + row * 512 + bn * 128 + tx * 8;
        float v[8];
#pragma unroll
        for (int j = 0; j < 4; j++) unpack2(v[2 * j], v[2 * j + 1], acc2[i][j]);
#pragma unroll
        for (int j = 0; j < 8; j++) v[j] += bi[j];
        *(float4*)(cp + 0) = make_float4(v[0], v[1], v[2], v[3]);
        *(float4*)(cp + 4) = make_float4(v[4], v[5], v[6], v[7]);
    }
}

// =====================================================================
// Kernel 2: recurrence. 32 clusters x 8 CTAs x 256 threads, 2 CTAs/SM.
// Cluster owns 2 batches. CTA rank rr owns W_hh[:, rr*64..rr*64+64):
//   warp w covers k in [64w, 64w+64); lane ln owns col-pair (2ln, 2ln+1);
//   k in [64w,64w+32) lives in REGISTERS (32 u64), k in [64w+32,64w+64)
//   in SMEM (conflict-free LDS.64).
// h pre-duplicated per k: {h0,h0,h1,h1} (16 B) -> inner loop is
// 1 LDS.128-broadcast + (reg or LDS.64 W) + 2 FFMA2 per k.
// Per step: GEMV -> smem split-K reduce + tanh -> 1 KB dup'd DSMEM
// broadcast to 8 ranks -> split cluster arrive/wait (xw prefetch in gap).
// =====================================================================
// float offsets in dynamic smem
#define WSM_OFF  0            // [8][32][32] u64 = 16384 floats (64 KB)
#define HB_OFF   16384        // [2][512][4] dup'd h = 4096 floats (16 KB)
#define RED_OFF  20480        // [16][33] u64 = 1056 floats
#define STG_OFF  21536        // [64][4] dup'd slice = 256 floats
#define K2_FLOATS (STG_OFF + 256)          // 21792
#define K2_SMEM_BYTES (K2_FLOATS * 4)      // 87,168 B  (x2 CTAs = 174 KB)

__global__ void __launch_bounds__(256, 2) __cluster_dims__(8, 1, 1)
rnn_rec_kernel(const float* __restrict__ W_hh, float* __restrict__ out) {
    extern __shared__ __align__(16) float smem[];
    u64*   wsm = (u64*)(smem + WSM_OFF);
    float* hb  = smem + HB_OFF;
    float* red = smem + RED_OFF;
    float* stg = smem + STG_OFF;

    const int tid = threadIdx.x;
    const uint32_t rr = ctarank();
    const int w  = tid >> 5;           // warp 0..7
    const int ln = tid & 31;           // col-pair index
    const int cluster = (int)(blockIdx.x >> 3);

    // ---- W: registers for k in [64w, 64w+32), smem for [64w+32, 64w+64) ----
    u64 wreg[32];
    {
        const u64* wg = (const u64*)(W_hh + (size_t)(64 * w) * 512 +
                                     rr * 64 + 2 * ln);
#pragma unroll
        for (int kk = 0; kk < 32; kk++) wreg[kk] = wg[(size_t)kk * 256];
        const u64* wg2 = (const u64*)(W_hh + (size_t)(64 * w + 32) * 512 +
                                      rr * 64 + 2 * ln);
        for (int kk = 0; kk < 32; kk++)
            wsm[(w * 32 + kk) * 32 + ln] = wg2[(size_t)kk * 256];
    }
    for (int i = tid; i < 4096; i += 256) hb[i] = 0.0f;
    __syncthreads();
    cluster_sync_();

    // reduce/output mapping (tid < 128): col rc, batch rb
    const int rc = tid & 63;
    const int rb = (tid >> 6) & 1;
    // broadcast mapping: warp w sends the full slice to rank w
    const uint32_t hb_s = smem_u32(hb);
    const uint32_t remR = mapa32(hb_s, (uint32_t)w);

    u64* redu = (u64*)red;
    const size_t obase = ((size_t)(cluster * 2 + rb) * 1024) * 512 +
                         (size_t)rr * 64 + rc;
    const float4* stg4 = (const float4*)stg;

    float xw_next = (tid < 128) ? out[obase] : 0.0f;

    for (int t = 0; t < 1024; t++) {
        const int j  = t & 1;       // buffer written this step (h_t)
        const int jr = j ^ 1;       // buffer read (h_{t-1})
        const float xw_v = xw_next;
        const size_t oidx = obase + (size_t)t * 512;

        // ---- GEMV: hybrid reg/smem W, dup'd-h broadcast loads ----
        u64 accA = 0ull, accB = 0ull;   // col-pair accum for b0, b1
        const ulonglong2* hp =
            (const ulonglong2*)(hb + (size_t)(jr * 512 + 64 * w) * 4);
#pragma unroll
        for (int kk = 0; kk < 32; kk++) {
            ulonglong2 hv = hp[kk];          // {h0,h0, h1,h1}
            accA = fma2(wreg[kk], hv.x, accA);
            accB = fma2(wreg[kk], hv.y, accB);
        }
        const u64* wq = wsm + (size_t)(w * 32) * 32 + ln;
#pragma unroll
        for (int kk = 0; kk < 32; kk++) {
            ulonglong2 hv = hp[32 + kk];
            u64 wk = wq[(size_t)kk * 32];
            accA = fma2(wk, hv.x, accA);
            accB = fma2(wk, hv.y, accB);
        }
        redu[(w * 2 + 0) * 33 + ln] = accA;
        redu[(w * 2 + 1) * 33 + ln] = accB;
        __syncthreads();

        // ---- reduce 8 partials + xw, tanh, store, stage dup'd ----
        if (tid < 128) {
            float s = xw_v;
#pragma unroll
            for (int ww = 0; ww < 8; ww++)
                s += red[(ww * 2 + rb) * 66 + rc];
            float h = tanhf(s);
            out[oidx] = h;
            *(u64*)(stg + rc * 4 + rb * 2) = dup2(h);
        }
        __syncthreads();

        // ---- 1 KB dup'd DSMEM broadcast (warp w -> rank w) + sync ----
        if (t < 1023) {
            float4 v0 = stg4[ln];
            float4 v1 = stg4[ln + 32];
            uint32_t base = (uint32_t)((j * 2048 + ((int)rr * 64) * 4) * 4);
            st_cluster_v4(remR + base + (uint32_t)ln * 16, v0);
            st_cluster_v4(remR + base + (uint32_t)(ln + 32) * 16, v1);
            cluster_arrive_();
            if (tid < 128) xw_next = out[oidx + 512];  // prefetch in gap
            cluster_wait_();
        }
    }
    cluster_sync_();
}

// =====================================================================
extern "C" void kernel_launch(void* const* d_in, const int* in_sizes, int n_in,
                              void* d_out, int out_size) {
    const float* inputs = (const float*)d_in[0];  // (64,1024,256)
    const float* W_xh   = (const float*)d_in[1];  // (256,512)
    const float* W_hh   = (const float*)d_in[2];  // (512,512)
    const float* b_h    = (const float*)d_in[3];  // (512,)
    float* out = (float*)d_out;                   // (64,1024,512)

    cudaFuncSetAttribute(rnn_rec_kernel,
                         cudaFuncAttributeMaxDynamicSharedMemorySize,
                         K2_SMEM_BYTES);

    dim3 g1(4, 512);
    xw_gemm_kernel<<<g1, 256>>>(inputs, W_xh, b_h, out);

    // 32 clusters x 8 CTAs, 2 batches per cluster, 2 CTAs per SM
    rnn_rec_kernel<<<256, 256, K2_SMEM_BYTES>>>(W_hh, out);
}